// round 1
// baseline (speedup 1.0000x reference)
#include <cuda_runtime.h>
#include <math.h>

// Problem constants
constexpr int BATCH = 2;
constexpr int SEQ   = 2048;
constexpr int DM    = 2048;
constexpr int NH    = 16;
constexpr int NKV   = 4;
constexpr int HDIM  = 128;
constexpr int HHALF = 64;
constexpr float EPSV = 1e-6f;
constexpr float SM_SCALE = 0.08838834764831845f; // 1/sqrt(128)

// Scratch (device globals — no runtime allocation)
__device__ float g_Qp[BATCH * SEQ * DM];          // q projection  [b*T+t][h*128+d]
__device__ float g_Kp[BATCH * SEQ * NKV * HDIM];  // k projection  [b*T+t][kh*128+d]
__device__ float g_Vp[BATCH * SEQ * NKV * HDIM];  // v projection  (used directly by flash)
__device__ float g_Qn[BATCH * SEQ * DM];          // q after rmsnorm+rope (same layout)
__device__ float g_Kn[BATCH * SEQ * NKV * HDIM];  // k after rmsnorm+rope
__device__ float g_Ob[BATCH * SEQ * DM];          // attention output [b*T+t][h*128+d]

// ---------------------------------------------------------------------------
// Tiled SGEMM: C[M,N] = A[M,K] @ B[K,N], all row-major fp32.
// 64x64 block tile, BK=16, 256 threads, 4x4 microtile per thread.
// ---------------------------------------------------------------------------
__global__ __launch_bounds__(256) void sgemm64(
    const float* __restrict__ A, const float* __restrict__ Bm,
    float* __restrict__ C, int M, int N, int K)
{
    __shared__ float As[16][64];   // transposed A tile: As[k][m]
    __shared__ float Bs[16][64];   // Bs[k][n]

    const int t  = threadIdx.x;
    const int tx = t & 15, ty = t >> 4;
    const int m0 = blockIdx.y * 64, n0 = blockIdx.x * 64;

    const int lar = t >> 2;            // A load row   0..63
    const int lak = (t & 3) << 2;      // A load k     0,4,8,12
    const int lbr = t >> 4;            // B load k     0..15
    const int lbn = (t & 15) << 2;     // B load n     0..60

    const float* Aptr = A + (size_t)(m0 + lar) * K + lak;
    const float* Bptr = Bm + (size_t)lbr * N + n0 + lbn;

    float acc[4][4] = {};

    for (int k0 = 0; k0 < K; k0 += 16) {
        float4 av = *(const float4*)(Aptr + k0);
        float4 bv = *(const float4*)(Bptr + (size_t)k0 * N);
        As[lak + 0][lar] = av.x;
        As[lak + 1][lar] = av.y;
        As[lak + 2][lar] = av.z;
        As[lak + 3][lar] = av.w;
        *(float4*)&Bs[lbr][lbn] = bv;
        __syncthreads();

#pragma unroll
        for (int kk = 0; kk < 16; kk++) {
            float4 a4 = *(const float4*)&As[kk][ty << 2];
            float4 b4 = *(const float4*)&Bs[kk][tx << 2];
            float ar[4] = {a4.x, a4.y, a4.z, a4.w};
            float br[4] = {b4.x, b4.y, b4.z, b4.w};
#pragma unroll
            for (int i = 0; i < 4; i++)
#pragma unroll
                for (int j = 0; j < 4; j++)
                    acc[i][j] = fmaf(ar[i], br[j], acc[i][j]);
        }
        __syncthreads();
    }

#pragma unroll
    for (int i = 0; i < 4; i++) {
        float4 o = make_float4(acc[i][0], acc[i][1], acc[i][2], acc[i][3]);
        *(float4*)&C[(size_t)(m0 + (ty << 2) + i) * N + n0 + (tx << 2)] = o;
    }
}

// ---------------------------------------------------------------------------
// Fused per-head RMSNorm + RoPE. One warp per (b, t, head).
// Input/output layout identical: [b*T+t][h*HDIM + d].
// ---------------------------------------------------------------------------
__global__ __launch_bounds__(256) void norm_rope(
    const float* __restrict__ P, const float* __restrict__ scale,
    const float* __restrict__ cs, const float* __restrict__ sn,
    float* __restrict__ out, int nh)
{
    const int gw   = (int)((blockIdx.x * blockDim.x + threadIdx.x) >> 5);
    const int lane = threadIdx.x & 31;
    const int h  = gw % nh;
    const int bt = gw / nh;          // 0 .. BATCH*SEQ-1
    const int tt = bt % SEQ;

    const size_t base = (size_t)bt * (nh * HDIM) + (size_t)h * HDIM;
    const int d = lane * 2;          // 0..62 even

    float2 lo = *(const float2*)&P[base + d];
    float2 hi = *(const float2*)&P[base + d + HHALF];

    float ss = lo.x * lo.x + lo.y * lo.y + hi.x * hi.x + hi.y * hi.y;
#pragma unroll
    for (int o = 16; o > 0; o >>= 1)
        ss += __shfl_xor_sync(0xffffffffu, ss, o);
    const float inv = rsqrtf(ss * (1.0f / HDIM) + EPSV);

    const float g0 = (1.0f + scale[d])          * inv;
    const float g1 = (1.0f + scale[d + 1])      * inv;
    const float g2 = (1.0f + scale[d + HHALF])  * inv;
    const float g3 = (1.0f + scale[d + 1 + HHALF]) * inv;

    const float x1a = lo.x * g0, x1b = lo.y * g1;
    const float x2a = hi.x * g2, x2b = hi.y * g3;

    const float c0 = cs[(size_t)tt * HHALF + d];
    const float c1 = cs[(size_t)tt * HHALF + d + 1];
    const float s0 = sn[(size_t)tt * HHALF + d];
    const float s1 = sn[(size_t)tt * HHALF + d + 1];

    float2 outlo = make_float2(x1a * c0 - x2a * s0, x1b * c1 - x2b * s1);
    float2 outhi = make_float2(x2a * c0 + x1a * s0, x2b * c1 + x1b * s1);
    *(float2*)&out[base + d]         = outlo;
    *(float2*)&out[base + d + HHALF] = outhi;
}

// ---------------------------------------------------------------------------
// Flash attention, fp32, causal, GQA (4 q-heads share one kv-head).
// Block = 256 threads, handles a 64-query tile for one (b, h).
// Loops over key tiles kt = 0..qt (causal tile skipping).
// ---------------------------------------------------------------------------
__global__ __launch_bounds__(256) void flash_attn(
    const float* __restrict__ Qn, const float* __restrict__ Kn,
    const float* __restrict__ Vp, float* __restrict__ Ob)
{
    extern __shared__ float smf[];
    float* Qs   = smf;                 // [64][129]
    float* Ks   = Qs + 64 * 129;       // [64][129]
    float* Vs   = Ks + 64 * 129;       // [64][128]
    float* Ss   = Vs + 64 * 128;       // [64][65]
    float* red  = Ss + 64 * 65;        // [64][4]
    float* mrow = red + 256;           // [64]
    float* lrow = mrow + 64;           // [64]
    float* arow = lrow + 64;           // [64]

    const int qt = blockIdx.x, h = blockIdx.y, b = blockIdx.z;
    const int t  = threadIdx.x;
    const int tx = t & 15, ty = t >> 4;
    const int q0 = qt * 64;
    const int kh = h >> 2;                        // h / (NH/NKV)

    const float* Qg = Qn + ((size_t)(b * SEQ + q0)) * DM + (size_t)h * HDIM;
    const float* Kg = Kn + (size_t)(b * SEQ) * (NKV * HDIM) + (size_t)kh * HDIM;
    const float* Vg = Vp + (size_t)(b * SEQ) * (NKV * HDIM) + (size_t)kh * HDIM;

    // Load Q tile (64 x 128). 256 threads x 32 floats.
    const int lr = t >> 2;              // row 0..63
    const int lc = (t & 3) << 5;        // col base 0,32,64,96
#pragma unroll
    for (int i = 0; i < 8; i++) {
        float4 v = *(const float4*)&Qg[(size_t)lr * DM + lc + i * 4];
        float* dst = &Qs[lr * 129 + lc + i * 4];
        dst[0] = v.x; dst[1] = v.y; dst[2] = v.z; dst[3] = v.w;
    }
    if (t < 64) { mrow[t] = -1e30f; lrow[t] = 0.0f; }

    float o[4][8];
#pragma unroll
    for (int i = 0; i < 4; i++)
#pragma unroll
        for (int j = 0; j < 8; j++) o[i][j] = 0.0f;

    const int rr = t >> 2, sg = t & 3;   // softmax-reduction row/segment

    for (int kt = 0; kt <= qt; kt++) {
        const int k0 = kt * 64;

        // Load K and V tiles
#pragma unroll
        for (int i = 0; i < 8; i++) {
            float4 kv = *(const float4*)&Kg[(size_t)(k0 + lr) * (NKV * HDIM) + lc + i * 4];
            float* kd = &Ks[lr * 129 + lc + i * 4];
            kd[0] = kv.x; kd[1] = kv.y; kd[2] = kv.z; kd[3] = kv.w;
            float4 vv = *(const float4*)&Vg[(size_t)(k0 + lr) * (NKV * HDIM) + lc + i * 4];
            *(float4*)&Vs[lr * 128 + lc + i * 4] = vv;
        }
        __syncthreads();   // A: tiles ready (also covers Q load on first iter)

        // S = Q K^T  (4x4 microtile per thread over 128 inner dim)
        float acc[4][4] = {};
        {
            const float* q0p = &Qs[(ty * 4 + 0) * 129];
            const float* q1p = &Qs[(ty * 4 + 1) * 129];
            const float* q2p = &Qs[(ty * 4 + 2) * 129];
            const float* q3p = &Qs[(ty * 4 + 3) * 129];
            const float* k0p = &Ks[(tx * 4 + 0) * 129];
            const float* k1p = &Ks[(tx * 4 + 1) * 129];
            const float* k2p = &Ks[(tx * 4 + 2) * 129];
            const float* k3p = &Ks[(tx * 4 + 3) * 129];
#pragma unroll 4
            for (int kk = 0; kk < 128; kk++) {
                float a0 = q0p[kk], a1 = q1p[kk], a2 = q2p[kk], a3 = q3p[kk];
                float b0 = k0p[kk], b1 = k1p[kk], b2 = k2p[kk], b3 = k3p[kk];
                acc[0][0] = fmaf(a0, b0, acc[0][0]);
                acc[0][1] = fmaf(a0, b1, acc[0][1]);
                acc[0][2] = fmaf(a0, b2, acc[0][2]);
                acc[0][3] = fmaf(a0, b3, acc[0][3]);
                acc[1][0] = fmaf(a1, b0, acc[1][0]);
                acc[1][1] = fmaf(a1, b1, acc[1][1]);
                acc[1][2] = fmaf(a1, b2, acc[1][2]);
                acc[1][3] = fmaf(a1, b3, acc[1][3]);
                acc[2][0] = fmaf(a2, b0, acc[2][0]);
                acc[2][1] = fmaf(a2, b1, acc[2][1]);
                acc[2][2] = fmaf(a2, b2, acc[2][2]);
                acc[2][3] = fmaf(a2, b3, acc[2][3]);
                acc[3][0] = fmaf(a3, b0, acc[3][0]);
                acc[3][1] = fmaf(a3, b1, acc[3][1]);
                acc[3][2] = fmaf(a3, b2, acc[3][2]);
                acc[3][3] = fmaf(a3, b3, acc[3][3]);
            }
        }

        // Scale + causal mask, write S to smem
#pragma unroll
        for (int i = 0; i < 4; i++) {
            const int qi = q0 + ty * 4 + i;
#pragma unroll
            for (int j = 0; j < 4; j++) {
                const int ki = k0 + tx * 4 + j;
                float v = acc[i][j] * SM_SCALE;
                if (ki > qi) v = -1e30f;
                Ss[(ty * 4 + i) * 65 + tx * 4 + j] = v;
            }
        }
        __syncthreads();   // B: Ss ready

        // Row max (4 partial segments of 16 per row)
        {
            float mx = -1e30f;
#pragma unroll
            for (int c = 0; c < 16; c++)
                mx = fmaxf(mx, Ss[rr * 65 + sg * 16 + c]);
            red[rr * 4 + sg] = mx;
        }
        __syncthreads();   // C

        if (t < 64) {
            float mt = fmaxf(fmaxf(red[t * 4], red[t * 4 + 1]),
                             fmaxf(red[t * 4 + 2], red[t * 4 + 3]));
            float mo = mrow[t];
            float mn = fmaxf(mo, mt);
            mrow[t] = mn;
            arow[t] = __expf(mo - mn);
        }
        __syncthreads();   // D: mrow/arow ready

        // exp pass + partial sums; rescale O registers
        {
            float al[4];
#pragma unroll
            for (int i = 0; i < 4; i++) al[i] = arow[ty * 4 + i];
#pragma unroll
            for (int i = 0; i < 4; i++)
#pragma unroll
                for (int j = 0; j < 8; j++) o[i][j] *= al[i];

            const float mn = mrow[rr];
            float sum = 0.0f;
#pragma unroll
            for (int c = 0; c < 16; c++) {
                float e = __expf(Ss[rr * 65 + sg * 16 + c] - mn);
                Ss[rr * 65 + sg * 16 + c] = e;
                sum += e;
            }
            red[rr * 4 + sg] = sum;
        }
        __syncthreads();   // E: P (=exp S) and partial sums ready

        if (t < 64)
            lrow[t] = lrow[t] * arow[t] +
                      red[t * 4] + red[t * 4 + 1] + red[t * 4 + 2] + red[t * 4 + 3];

        // O += P @ V
#pragma unroll 2
        for (int c = 0; c < 64; c++) {
            float p0 = Ss[(ty * 4 + 0) * 65 + c];
            float p1 = Ss[(ty * 4 + 1) * 65 + c];
            float p2 = Ss[(ty * 4 + 2) * 65 + c];
            float p3 = Ss[(ty * 4 + 3) * 65 + c];
            float4 va = *(const float4*)&Vs[c * 128 + tx * 4];
            float4 vb = *(const float4*)&Vs[c * 128 + tx * 4 + 64];
            o[0][0] = fmaf(p0, va.x, o[0][0]);
            o[0][1] = fmaf(p0, va.y, o[0][1]);
            o[0][2] = fmaf(p0, va.z, o[0][2]);
            o[0][3] = fmaf(p0, va.w, o[0][3]);
            o[0][4] = fmaf(p0, vb.x, o[0][4]);
            o[0][5] = fmaf(p0, vb.y, o[0][5]);
            o[0][6] = fmaf(p0, vb.z, o[0][6]);
            o[0][7] = fmaf(p0, vb.w, o[0][7]);
            o[1][0] = fmaf(p1, va.x, o[1][0]);
            o[1][1] = fmaf(p1, va.y, o[1][1]);
            o[1][2] = fmaf(p1, va.z, o[1][2]);
            o[1][3] = fmaf(p1, va.w, o[1][3]);
            o[1][4] = fmaf(p1, vb.x, o[1][4]);
            o[1][5] = fmaf(p1, vb.y, o[1][5]);
            o[1][6] = fmaf(p1, vb.z, o[1][6]);
            o[1][7] = fmaf(p1, vb.w, o[1][7]);
            o[2][0] = fmaf(p2, va.x, o[2][0]);
            o[2][1] = fmaf(p2, va.y, o[2][1]);
            o[2][2] = fmaf(p2, va.z, o[2][2]);
            o[2][3] = fmaf(p2, va.w, o[2][3]);
            o[2][4] = fmaf(p2, vb.x, o[2][4]);
            o[2][5] = fmaf(p2, vb.y, o[2][5]);
            o[2][6] = fmaf(p2, vb.z, o[2][6]);
            o[2][7] = fmaf(p2, vb.w, o[2][7]);
            o[3][0] = fmaf(p3, va.x, o[3][0]);
            o[3][1] = fmaf(p3, va.y, o[3][1]);
            o[3][2] = fmaf(p3, va.z, o[3][2]);
            o[3][3] = fmaf(p3, va.w, o[3][3]);
            o[3][4] = fmaf(p3, vb.x, o[3][4]);
            o[3][5] = fmaf(p3, vb.y, o[3][5]);
            o[3][6] = fmaf(p3, vb.z, o[3][6]);
            o[3][7] = fmaf(p3, vb.w, o[3][7]);
        }
        __syncthreads();   // F: safe to reuse tiles
    }

    // Final normalize + write out in [b*T+q][h*128+d] layout
#pragma unroll
    for (int i = 0; i < 4; i++) {
        const float inv = 1.0f / lrow[ty * 4 + i];
        const int q = q0 + ty * 4 + i;
        float* dst = &Ob[((size_t)(b * SEQ + q)) * DM + (size_t)h * HDIM + tx * 4];
        float4 oa = make_float4(o[i][0] * inv, o[i][1] * inv, o[i][2] * inv, o[i][3] * inv);
        float4 ob = make_float4(o[i][4] * inv, o[i][5] * inv, o[i][6] * inv, o[i][7] * inv);
        *(float4*)dst        = oa;
        *(float4*)(dst + 64) = ob;
    }
}

// ---------------------------------------------------------------------------
// Launch
// ---------------------------------------------------------------------------
extern "C" void kernel_launch(void* const* d_in, const int* in_sizes, int n_in,
                              void* d_out, int out_size)
{
    const float* q_input  = (const float*)d_in[0];
    const float* kv_input = (const float*)d_in[1];
    // d_in[2] = mask (unused: causal structure is known)
    const float* cosb     = (const float*)d_in[3];
    const float* sinb     = (const float*)d_in[4];
    const float* Wq       = (const float*)d_in[5];
    const float* Wk       = (const float*)d_in[6];
    const float* Wv       = (const float*)d_in[7];
    const float* q_scale  = (const float*)d_in[8];
    const float* k_scale  = (const float*)d_in[9];
    const float* Wo       = (const float*)d_in[10];
    float* out = (float*)d_out;

    float *Qp, *Kp, *Vp, *Qn, *Kn, *Ob;
    cudaGetSymbolAddress((void**)&Qp, g_Qp);
    cudaGetSymbolAddress((void**)&Kp, g_Kp);
    cudaGetSymbolAddress((void**)&Vp, g_Vp);
    cudaGetSymbolAddress((void**)&Qn, g_Qn);
    cudaGetSymbolAddress((void**)&Kn, g_Kn);
    cudaGetSymbolAddress((void**)&Ob, g_Ob);

    const int FLASH_SMEM = (64 * 129 * 2 + 64 * 128 + 64 * 65 + 256 + 64 * 3) * 4;
    cudaFuncSetAttribute(flash_attn, cudaFuncAttributeMaxDynamicSharedMemorySize,
                         FLASH_SMEM);

    const int MROWS = BATCH * SEQ; // 4096
    dim3 blk(256);

    // Projections
    sgemm64<<<dim3(DM / 64, MROWS / 64), blk>>>(q_input, Wq, Qp, MROWS, DM, DM);
    sgemm64<<<dim3((NKV * HDIM) / 64, MROWS / 64), blk>>>(kv_input, Wk, Kp, MROWS, NKV * HDIM, DM);
    sgemm64<<<dim3((NKV * HDIM) / 64, MROWS / 64), blk>>>(kv_input, Wv, Vp, MROWS, NKV * HDIM, DM);

    // RMSNorm + RoPE (V passes through untouched)
    norm_rope<<<(BATCH * SEQ * NH) / 8, blk>>>(Qp, q_scale, cosb, sinb, Qn, NH);
    norm_rope<<<(BATCH * SEQ * NKV) / 8, blk>>>(Kp, k_scale, cosb, sinb, Kn, NKV);

    // Causal flash attention with GQA
    flash_attn<<<dim3(SEQ / 64, NH, BATCH), blk, FLASH_SMEM>>>(Qn, Kn, Vp, Ob);

    // Output projection
    sgemm64<<<dim3(DM / 64, MROWS / 64), blk>>>(Ob, Wo, out, MROWS, DM, DM);
}

// round 3
// speedup vs baseline: 1.6056x; 1.6056x over previous
#include <cuda_runtime.h>
#include <cuda_bf16.h>
#include <math.h>
#include <stdint.h>

// Problem constants
constexpr int BATCH = 2;
constexpr int SEQ   = 2048;
constexpr int DM    = 2048;
constexpr int NH    = 16;
constexpr int NKV   = 4;
constexpr int HDIM  = 128;
constexpr int HHALF = 64;
constexpr float EPSV = 1e-6f;
constexpr float SM_SCALE = 0.08838834764831845f; // 1/sqrt(128)
constexpr int MR  = BATCH * SEQ;                  // 4096 rows
constexpr int KVD = NKV * HDIM;                   // 512

// ---------------- scratch (device globals — no runtime allocation) --------
__device__ float g_Qp[MR * DM];
__device__ float g_Kp[MR * KVD];
__device__ float g_Vp[MR * KVD];
__device__ float g_Qn[MR * DM];
__device__ float g_Kn[MR * KVD];
__device__ float g_Ob[MR * DM];

__device__ __nv_bfloat16 g_Aq_h[MR * DM],  g_Aq_l[MR * DM];
__device__ __nv_bfloat16 g_Akv_h[MR * DM], g_Akv_l[MR * DM];
__device__ __nv_bfloat16 g_Ao_h[MR * DM],  g_Ao_l[MR * DM];
__device__ __nv_bfloat16 g_WqT_h[DM * DM],  g_WqT_l[DM * DM];
__device__ __nv_bfloat16 g_WkT_h[KVD * DM], g_WkT_l[KVD * DM];
__device__ __nv_bfloat16 g_WvT_h[KVD * DM], g_WvT_l[KVD * DM];
__device__ __nv_bfloat16 g_WoT_h[DM * DM],  g_WoT_l[DM * DM];

// ---------------------------------------------------------------------------
// Helpers (baseline PTX only: cp.async, ldmatrix, mma.sync — no 'a' features)
// ---------------------------------------------------------------------------
__device__ __forceinline__ uint32_t smem_u32(const void* p) {
    uint32_t a;
    asm("{ .reg .u64 t; cvta.to.shared.u64 t, %1; cvt.u32.u64 %0, t; }"
        : "=r"(a) : "l"(p));
    return a;
}

__device__ __forceinline__ void cp16(uint32_t dst, const void* src) {
    asm volatile("cp.async.cg.shared.global [%0], [%1], 16;" :: "r"(dst), "l"(src));
}
__device__ __forceinline__ void cp_commit() {
    asm volatile("cp.async.commit_group;" ::: "memory");
}
template <int N>
__device__ __forceinline__ void cp_wait() {
    asm volatile("cp.async.wait_group %0;" :: "n"(N) : "memory");
}

__device__ __forceinline__ void ldsm4(uint32_t& r0, uint32_t& r1, uint32_t& r2,
                                      uint32_t& r3, uint32_t addr) {
    asm volatile("ldmatrix.sync.aligned.m8n8.x4.shared.b16 {%0,%1,%2,%3}, [%4];"
                 : "=r"(r0), "=r"(r1), "=r"(r2), "=r"(r3) : "r"(addr));
}

__device__ __forceinline__ void mma_bf16(float* c, const uint32_t* a,
                                         const uint32_t* b) {
    asm volatile(
        "mma.sync.aligned.m16n8k16.row.col.f32.bf16.bf16.f32 "
        "{%0,%1,%2,%3}, {%4,%5,%6,%7}, {%8,%9}, {%0,%1,%2,%3};"
        : "+f"(c[0]), "+f"(c[1]), "+f"(c[2]), "+f"(c[3])
        : "r"(a[0]), "r"(a[1]), "r"(a[2]), "r"(a[3]), "r"(b[0]), "r"(b[1]));
}

// ---------------------------------------------------------------------------
// hi/lo bf16 split, elementwise (row-major layout preserved)
// ---------------------------------------------------------------------------
__global__ __launch_bounds__(256) void split_rows(
    const float* __restrict__ X, __nv_bfloat16* __restrict__ Hh,
    __nv_bfloat16* __restrict__ Ll, int n4)
{
    int i = blockIdx.x * blockDim.x + threadIdx.x;
    if (i >= n4) return;
    float4 v = ((const float4*)X)[i];
    __nv_bfloat16 h0 = __float2bfloat16(v.x);
    __nv_bfloat16 h1 = __float2bfloat16(v.y);
    __nv_bfloat16 h2 = __float2bfloat16(v.z);
    __nv_bfloat16 h3 = __float2bfloat16(v.w);
    __nv_bfloat162* Hp = (__nv_bfloat162*)Hh;
    Hp[2 * i]     = __nv_bfloat162(h0, h1);
    Hp[2 * i + 1] = __nv_bfloat162(h2, h3);
    __nv_bfloat16 l0 = __float2bfloat16(v.x - __bfloat162float(h0));
    __nv_bfloat16 l1 = __float2bfloat16(v.y - __bfloat162float(h1));
    __nv_bfloat16 l2 = __float2bfloat16(v.z - __bfloat162float(h2));
    __nv_bfloat16 l3 = __float2bfloat16(v.w - __bfloat162float(h3));
    __nv_bfloat162* Lp = (__nv_bfloat162*)Ll;
    Lp[2 * i]     = __nv_bfloat162(l0, l1);
    Lp[2 * i + 1] = __nv_bfloat162(l2, l3);
}

// ---------------------------------------------------------------------------
// Transpose + hi/lo split: W[K,N] fp32 -> WT_hi/WT_lo [N,K] bf16
// ---------------------------------------------------------------------------
__global__ __launch_bounds__(256) void split_transpose(
    const float* __restrict__ W, __nv_bfloat16* __restrict__ TH,
    __nv_bfloat16* __restrict__ TL, int K, int N)
{
    __shared__ float tile[32][33];
    const int k0 = blockIdx.x * 32, n0 = blockIdx.y * 32;
    const int tx = threadIdx.x, ty = threadIdx.y;     // 32 x 8
#pragma unroll
    for (int i = 0; i < 4; i++)
        tile[ty + i * 8][tx] = W[(size_t)(k0 + ty + i * 8) * N + n0 + tx];
    __syncthreads();
#pragma unroll
    for (int i = 0; i < 4; i++) {
        float v = tile[tx][ty + i * 8];               // = W[k0+tx][n0+ty+i*8]
        int n = n0 + ty + i * 8;
        __nv_bfloat16 h = __float2bfloat16(v);
        TH[(size_t)n * K + k0 + tx] = h;
        TL[(size_t)n * K + k0 + tx] = __float2bfloat16(v - __bfloat162float(h));
    }
}

// ---------------------------------------------------------------------------
// bf16 tensor-core GEMM with 3-term hi/lo split accumulation (mma.sync).
// C[4096, N] = Ahi@Bhi^T + Alo@Bhi^T + Ahi@Blo^T, each section K=2048.
// B given transposed: Bt[n][k] (k contiguous).
// Block tile 128x128, BK=64, double-buffered cp.async, 8 warps (2x4),
// warp tile 64x32 via m16n8k16.
// ---------------------------------------------------------------------------
constexpr int LDT    = 72;                 // padded bf16 per smem row (64+8)
constexpr int ABYTES = 128 * LDT * 2;      // 18432 B per matrix tile
constexpr int STAGEB = 2 * ABYTES;         // A+B per stage = 36864 B
constexpr int GEMM_SMEM = 2 * STAGEB;      // 73728 B

__global__ __launch_bounds__(256, 2) void gemm3s(
    const __nv_bfloat16* __restrict__ Ahi, const __nv_bfloat16* __restrict__ Alo,
    const __nv_bfloat16* __restrict__ Bhi, const __nv_bfloat16* __restrict__ Blo,
    float* __restrict__ C, int N)
{
    extern __shared__ __align__(16) char smg[];
    const uint32_t sb = smem_u32(smg);
    const int t = threadIdx.x, lane = t & 31, wid = t >> 5;
    const int wm = wid & 1, wn = wid >> 1;          // 2 x 4 warp grid
    const int m0 = blockIdx.y * 128, n0 = blockIdx.x * 128;

    float acc[4][4][4] = {};

    // loader indices: 2048 16B-chunks per stage (1024 A + 1024 B)
    const int lrow = t >> 3;            // base row step for chunk mapping
    const int lch  = t & 7;

    const int NIT = 96;                 // 3 sections * 32 BK-iters

    auto load_stage = [&](int it, int s) {
        const int sec  = it >> 5;
        const int koff = (it & 31) << 6;
        const __nv_bfloat16* Ag = (sec == 1 ? Alo : Ahi);
        const __nv_bfloat16* Bg = (sec == 2 ? Blo : Bhi);
        const uint32_t Ab = sb + s * STAGEB;
        const uint32_t Bb = Ab + ABYTES;
#pragma unroll
        for (int i = 0; i < 4; i++) {
            const int row = lrow + i * 32;          // 0..127
            cp16(Ab + row * (LDT * 2) + lch * 16,
                 Ag + (size_t)(m0 + row) * DM + koff + lch * 8);
            cp16(Bb + row * (LDT * 2) + lch * 16,
                 Bg + (size_t)(n0 + row) * DM + koff + lch * 8);
        }
        cp_commit();
    };

    load_stage(0, 0);

    // fragment address components (constant across iters except stage base)
    const uint32_t a_off = (uint32_t)((wm * 64 + (lane & 15)) * (LDT * 2) +
                                      ((lane >> 4) << 4));
    const uint32_t b_off = (uint32_t)((wn * 32 + ((lane >> 4) << 3) + (lane & 7)) * (LDT * 2) +
                                      (((lane >> 3) & 1) << 4));

    for (int it = 0; it < NIT; it++) {
        if (it + 1 < NIT) {
            load_stage(it + 1, (it + 1) & 1);
            cp_wait<1>();
        } else {
            cp_wait<0>();
        }
        __syncthreads();

        const uint32_t Ab = sb + (it & 1) * STAGEB;
        const uint32_t Bb = Ab + ABYTES;

#pragma unroll
        for (int ks = 0; ks < 4; ks++) {
            uint32_t a[4][4];
            uint32_t b[4][2];
#pragma unroll
            for (int i = 0; i < 4; i++)
                ldsm4(a[i][0], a[i][1], a[i][2], a[i][3],
                      Ab + a_off + i * 16 * (LDT * 2) + ks * 32);
#pragma unroll
            for (int j = 0; j < 2; j++) {
                uint32_t r0, r1, r2, r3;
                ldsm4(r0, r1, r2, r3,
                      Bb + b_off + j * 16 * (LDT * 2) + ks * 32);
                b[j * 2][0] = r0; b[j * 2][1] = r1;
                b[j * 2 + 1][0] = r2; b[j * 2 + 1][1] = r3;
            }
#pragma unroll
            for (int i = 0; i < 4; i++)
#pragma unroll
                for (int j = 0; j < 4; j++)
                    mma_bf16(acc[i][j], a[i], b[j]);
        }
        __syncthreads();
    }

    // epilogue: direct fp32 stores
#pragma unroll
    for (int i = 0; i < 4; i++) {
#pragma unroll
        for (int j = 0; j < 4; j++) {
            const int m = m0 + wm * 64 + i * 16 + (lane >> 2);
            const int n = n0 + wn * 32 + j * 8 + ((lane & 3) << 1);
            *(float2*)&C[(size_t)m * N + n] =
                make_float2(acc[i][j][0], acc[i][j][1]);
            *(float2*)&C[(size_t)(m + 8) * N + n] =
                make_float2(acc[i][j][2], acc[i][j][3]);
        }
    }
}

// ---------------------------------------------------------------------------
// Fused per-head RMSNorm + RoPE
// ---------------------------------------------------------------------------
__global__ __launch_bounds__(256) void norm_rope(
    const float* __restrict__ P, const float* __restrict__ scale,
    const float* __restrict__ cs, const float* __restrict__ sn,
    float* __restrict__ out, int nh)
{
    const int gw   = (int)((blockIdx.x * blockDim.x + threadIdx.x) >> 5);
    const int lane = threadIdx.x & 31;
    const int h  = gw % nh;
    const int bt = gw / nh;
    const int tt = bt % SEQ;

    const size_t base = (size_t)bt * (nh * HDIM) + (size_t)h * HDIM;
    const int d = lane * 2;

    float2 lo = *(const float2*)&P[base + d];
    float2 hi = *(const float2*)&P[base + d + HHALF];

    float ss = lo.x * lo.x + lo.y * lo.y + hi.x * hi.x + hi.y * hi.y;
#pragma unroll
    for (int o = 16; o > 0; o >>= 1)
        ss += __shfl_xor_sync(0xffffffffu, ss, o);
    const float inv = rsqrtf(ss * (1.0f / HDIM) + EPSV);

    const float g0 = (1.0f + scale[d])             * inv;
    const float g1 = (1.0f + scale[d + 1])         * inv;
    const float g2 = (1.0f + scale[d + HHALF])     * inv;
    const float g3 = (1.0f + scale[d + 1 + HHALF]) * inv;

    const float x1a = lo.x * g0, x1b = lo.y * g1;
    const float x2a = hi.x * g2, x2b = hi.y * g3;

    const float c0 = cs[(size_t)tt * HHALF + d];
    const float c1 = cs[(size_t)tt * HHALF + d + 1];
    const float s0 = sn[(size_t)tt * HHALF + d];
    const float s1 = sn[(size_t)tt * HHALF + d + 1];

    *(float2*)&out[base + d]         = make_float2(x1a * c0 - x2a * s0, x1b * c1 - x2b * s1);
    *(float2*)&out[base + d + HHALF] = make_float2(x2a * c0 + x1a * s0, x2b * c1 + x1b * s1);
}

// ---------------------------------------------------------------------------
// Flash attention fp32 (unchanged)
// ---------------------------------------------------------------------------
__global__ __launch_bounds__(256) void flash_attn(
    const float* __restrict__ Qn, const float* __restrict__ Kn,
    const float* __restrict__ Vp, float* __restrict__ Ob)
{
    extern __shared__ float smf[];
    float* Qs   = smf;
    float* Ks   = Qs + 64 * 129;
    float* Vs   = Ks + 64 * 129;
    float* Ss   = Vs + 64 * 128;
    float* red  = Ss + 64 * 65;
    float* mrow = red + 256;
    float* lrow = mrow + 64;
    float* arow = lrow + 64;

    const int qt = blockIdx.x, h = blockIdx.y, b = blockIdx.z;
    const int t  = threadIdx.x;
    const int tx = t & 15, ty = t >> 4;
    const int q0 = qt * 64;
    const int kh = h >> 2;

    const float* Qg = Qn + ((size_t)(b * SEQ + q0)) * DM + (size_t)h * HDIM;
    const float* Kg = Kn + (size_t)(b * SEQ) * KVD + (size_t)kh * HDIM;
    const float* Vg = Vp + (size_t)(b * SEQ) * KVD + (size_t)kh * HDIM;

    const int lr = t >> 2;
    const int lc = (t & 3) << 5;
#pragma unroll
    for (int i = 0; i < 8; i++) {
        float4 v = *(const float4*)&Qg[(size_t)lr * DM + lc + i * 4];
        float* dst = &Qs[lr * 129 + lc + i * 4];
        dst[0] = v.x; dst[1] = v.y; dst[2] = v.z; dst[3] = v.w;
    }
    if (t < 64) { mrow[t] = -1e30f; lrow[t] = 0.0f; }

    float o[4][8];
#pragma unroll
    for (int i = 0; i < 4; i++)
#pragma unroll
        for (int j = 0; j < 8; j++) o[i][j] = 0.0f;

    const int rr = t >> 2, sg = t & 3;

    for (int kt = 0; kt <= qt; kt++) {
        const int k0 = kt * 64;
#pragma unroll
        for (int i = 0; i < 8; i++) {
            float4 kv = *(const float4*)&Kg[(size_t)(k0 + lr) * KVD + lc + i * 4];
            float* kd = &Ks[lr * 129 + lc + i * 4];
            kd[0] = kv.x; kd[1] = kv.y; kd[2] = kv.z; kd[3] = kv.w;
            float4 vv = *(const float4*)&Vg[(size_t)(k0 + lr) * KVD + lc + i * 4];
            *(float4*)&Vs[lr * 128 + lc + i * 4] = vv;
        }
        __syncthreads();

        float acc[4][4] = {};
        {
            const float* q0p = &Qs[(ty * 4 + 0) * 129];
            const float* q1p = &Qs[(ty * 4 + 1) * 129];
            const float* q2p = &Qs[(ty * 4 + 2) * 129];
            const float* q3p = &Qs[(ty * 4 + 3) * 129];
            const float* k0p = &Ks[(tx * 4 + 0) * 129];
            const float* k1p = &Ks[(tx * 4 + 1) * 129];
            const float* k2p = &Ks[(tx * 4 + 2) * 129];
            const float* k3p = &Ks[(tx * 4 + 3) * 129];
#pragma unroll 4
            for (int kk = 0; kk < 128; kk++) {
                float a0 = q0p[kk], a1 = q1p[kk], a2 = q2p[kk], a3 = q3p[kk];
                float b0 = k0p[kk], b1 = k1p[kk], b2 = k2p[kk], b3 = k3p[kk];
                acc[0][0] = fmaf(a0, b0, acc[0][0]);
                acc[0][1] = fmaf(a0, b1, acc[0][1]);
                acc[0][2] = fmaf(a0, b2, acc[0][2]);
                acc[0][3] = fmaf(a0, b3, acc[0][3]);
                acc[1][0] = fmaf(a1, b0, acc[1][0]);
                acc[1][1] = fmaf(a1, b1, acc[1][1]);
                acc[1][2] = fmaf(a1, b2, acc[1][2]);
                acc[1][3] = fmaf(a1, b3, acc[1][3]);
                acc[2][0] = fmaf(a2, b0, acc[2][0]);
                acc[2][1] = fmaf(a2, b1, acc[2][1]);
                acc[2][2] = fmaf(a2, b2, acc[2][2]);
                acc[2][3] = fmaf(a2, b3, acc[2][3]);
                acc[3][0] = fmaf(a3, b0, acc[3][0]);
                acc[3][1] = fmaf(a3, b1, acc[3][1]);
                acc[3][2] = fmaf(a3, b2, acc[3][2]);
                acc[3][3] = fmaf(a3, b3, acc[3][3]);
            }
        }

#pragma unroll
        for (int i = 0; i < 4; i++) {
            const int qi = q0 + ty * 4 + i;
#pragma unroll
            for (int j = 0; j < 4; j++) {
                const int ki = k0 + tx * 4 + j;
                float v = acc[i][j] * SM_SCALE;
                if (ki > qi) v = -1e30f;
                Ss[(ty * 4 + i) * 65 + tx * 4 + j] = v;
            }
        }
        __syncthreads();

        {
            float mx = -1e30f;
#pragma unroll
            for (int c = 0; c < 16; c++)
                mx = fmaxf(mx, Ss[rr * 65 + sg * 16 + c]);
            red[rr * 4 + sg] = mx;
        }
        __syncthreads();

        if (t < 64) {
            float mt = fmaxf(fmaxf(red[t * 4], red[t * 4 + 1]),
                             fmaxf(red[t * 4 + 2], red[t * 4 + 3]));
            float mo = mrow[t];
            float mn = fmaxf(mo, mt);
            mrow[t] = mn;
            arow[t] = __expf(mo - mn);
        }
        __syncthreads();

        {
            float al[4];
#pragma unroll
            for (int i = 0; i < 4; i++) al[i] = arow[ty * 4 + i];
#pragma unroll
            for (int i = 0; i < 4; i++)
#pragma unroll
                for (int j = 0; j < 8; j++) o[i][j] *= al[i];

            const float mn = mrow[rr];
            float sum = 0.0f;
#pragma unroll
            for (int c = 0; c < 16; c++) {
                float e = __expf(Ss[rr * 65 + sg * 16 + c] - mn);
                Ss[rr * 65 + sg * 16 + c] = e;
                sum += e;
            }
            red[rr * 4 + sg] = sum;
        }
        __syncthreads();

        if (t < 64)
            lrow[t] = lrow[t] * arow[t] +
                      red[t * 4] + red[t * 4 + 1] + red[t * 4 + 2] + red[t * 4 + 3];

#pragma unroll 2
        for (int c = 0; c < 64; c++) {
            float p0 = Ss[(ty * 4 + 0) * 65 + c];
            float p1 = Ss[(ty * 4 + 1) * 65 + c];
            float p2 = Ss[(ty * 4 + 2) * 65 + c];
            float p3 = Ss[(ty * 4 + 3) * 65 + c];
            float4 va = *(const float4*)&Vs[c * 128 + tx * 4];
            float4 vb = *(const float4*)&Vs[c * 128 + tx * 4 + 64];
            o[0][0] = fmaf(p0, va.x, o[0][0]);
            o[0][1] = fmaf(p0, va.y, o[0][1]);
            o[0][2] = fmaf(p0, va.z, o[0][2]);
            o[0][3] = fmaf(p0, va.w, o[0][3]);
            o[0][4] = fmaf(p0, vb.x, o[0][4]);
            o[0][5] = fmaf(p0, vb.y, o[0][5]);
            o[0][6] = fmaf(p0, vb.z, o[0][6]);
            o[0][7] = fmaf(p0, vb.w, o[0][7]);
            o[1][0] = fmaf(p1, va.x, o[1][0]);
            o[1][1] = fmaf(p1, va.y, o[1][1]);
            o[1][2] = fmaf(p1, va.z, o[1][2]);
            o[1][3] = fmaf(p1, va.w, o[1][3]);
            o[1][4] = fmaf(p1, vb.x, o[1][4]);
            o[1][5] = fmaf(p1, vb.y, o[1][5]);
            o[1][6] = fmaf(p1, vb.z, o[1][6]);
            o[1][7] = fmaf(p1, vb.w, o[1][7]);
            o[2][0] = fmaf(p2, va.x, o[2][0]);
            o[2][1] = fmaf(p2, va.y, o[2][1]);
            o[2][2] = fmaf(p2, va.z, o[2][2]);
            o[2][3] = fmaf(p2, va.w, o[2][3]);
            o[2][4] = fmaf(p2, vb.x, o[2][4]);
            o[2][5] = fmaf(p2, vb.y, o[2][5]);
            o[2][6] = fmaf(p2, vb.z, o[2][6]);
            o[2][7] = fmaf(p2, vb.w, o[2][7]);
            o[3][0] = fmaf(p3, va.x, o[3][0]);
            o[3][1] = fmaf(p3, va.y, o[3][1]);
            o[3][2] = fmaf(p3, va.z, o[3][2]);
            o[3][3] = fmaf(p3, va.w, o[3][3]);
            o[3][4] = fmaf(p3, vb.x, o[3][4]);
            o[3][5] = fmaf(p3, vb.y, o[3][5]);
            o[3][6] = fmaf(p3, vb.z, o[3][6]);
            o[3][7] = fmaf(p3, vb.w, o[3][7]);
        }
        __syncthreads();
    }

#pragma unroll
    for (int i = 0; i < 4; i++) {
        const float inv = 1.0f / lrow[ty * 4 + i];
        const int q = q0 + ty * 4 + i;
        float* dst = &Ob[((size_t)(b * SEQ + q)) * DM + (size_t)h * HDIM + tx * 4];
        *(float4*)dst = make_float4(o[i][0] * inv, o[i][1] * inv, o[i][2] * inv, o[i][3] * inv);
        *(float4*)(dst + 64) = make_float4(o[i][4] * inv, o[i][5] * inv, o[i][6] * inv, o[i][7] * inv);
    }
}

// ---------------------------------------------------------------------------
// Launch
// ---------------------------------------------------------------------------
extern "C" void kernel_launch(void* const* d_in, const int* in_sizes, int n_in,
                              void* d_out, int out_size)
{
    const float* q_input  = (const float*)d_in[0];
    const float* kv_input = (const float*)d_in[1];
    const float* cosb     = (const float*)d_in[3];
    const float* sinb     = (const float*)d_in[4];
    const float* Wq       = (const float*)d_in[5];
    const float* Wk       = (const float*)d_in[6];
    const float* Wv       = (const float*)d_in[7];
    const float* q_scale  = (const float*)d_in[8];
    const float* k_scale  = (const float*)d_in[9];
    const float* Wo       = (const float*)d_in[10];
    float* out = (float*)d_out;

    float *Qp, *Kp, *Vp, *Qn, *Kn, *Ob;
    cudaGetSymbolAddress((void**)&Qp, g_Qp);
    cudaGetSymbolAddress((void**)&Kp, g_Kp);
    cudaGetSymbolAddress((void**)&Vp, g_Vp);
    cudaGetSymbolAddress((void**)&Qn, g_Qn);
    cudaGetSymbolAddress((void**)&Kn, g_Kn);
    cudaGetSymbolAddress((void**)&Ob, g_Ob);

    __nv_bfloat16 *Aqh, *Aql, *Akh, *Akl, *Aoh, *Aol;
    __nv_bfloat16 *WqTh, *WqTl, *WkTh, *WkTl, *WvTh, *WvTl, *WoTh, *WoTl;
    cudaGetSymbolAddress((void**)&Aqh, g_Aq_h);
    cudaGetSymbolAddress((void**)&Aql, g_Aq_l);
    cudaGetSymbolAddress((void**)&Akh, g_Akv_h);
    cudaGetSymbolAddress((void**)&Akl, g_Akv_l);
    cudaGetSymbolAddress((void**)&Aoh, g_Ao_h);
    cudaGetSymbolAddress((void**)&Aol, g_Ao_l);
    cudaGetSymbolAddress((void**)&WqTh, g_WqT_h);
    cudaGetSymbolAddress((void**)&WqTl, g_WqT_l);
    cudaGetSymbolAddress((void**)&WkTh, g_WkT_h);
    cudaGetSymbolAddress((void**)&WkTl, g_WkT_l);
    cudaGetSymbolAddress((void**)&WvTh, g_WvT_h);
    cudaGetSymbolAddress((void**)&WvTl, g_WvT_l);
    cudaGetSymbolAddress((void**)&WoTh, g_WoT_h);
    cudaGetSymbolAddress((void**)&WoTl, g_WoT_l);

    cudaFuncSetAttribute(gemm3s, cudaFuncAttributeMaxDynamicSharedMemorySize,
                         GEMM_SMEM);
    const int FLASH_SMEM = (64 * 129 * 2 + 64 * 128 + 64 * 65 + 256 + 64 * 3) * 4;
    cudaFuncSetAttribute(flash_attn, cudaFuncAttributeMaxDynamicSharedMemorySize,
                         FLASH_SMEM);

    dim3 blk(256);

    // hi/lo splits of activations and (transposed) weights
    split_rows<<<(MR * DM / 4 + 255) / 256, blk>>>(q_input, Aqh, Aql, MR * DM / 4);
    split_rows<<<(MR * DM / 4 + 255) / 256, blk>>>(kv_input, Akh, Akl, MR * DM / 4);
    split_transpose<<<dim3(DM / 32, DM / 32), dim3(32, 8)>>>(Wq, WqTh, WqTl, DM, DM);
    split_transpose<<<dim3(DM / 32, KVD / 32), dim3(32, 8)>>>(Wk, WkTh, WkTl, DM, KVD);
    split_transpose<<<dim3(DM / 32, KVD / 32), dim3(32, 8)>>>(Wv, WvTh, WvTl, DM, KVD);
    split_transpose<<<dim3(DM / 32, DM / 32), dim3(32, 8)>>>(Wo, WoTh, WoTl, DM, DM);

    // tensor-core projections (3-term split)
    gemm3s<<<dim3(DM / 128, MR / 128), blk, GEMM_SMEM>>>(Aqh, Aql, WqTh, WqTl, Qp, DM);
    gemm3s<<<dim3(KVD / 128, MR / 128), blk, GEMM_SMEM>>>(Akh, Akl, WkTh, WkTl, Kp, KVD);
    gemm3s<<<dim3(KVD / 128, MR / 128), blk, GEMM_SMEM>>>(Akh, Akl, WvTh, WvTl, Vp, KVD);

    // RMSNorm + RoPE
    norm_rope<<<(MR * NH) / 8, blk>>>(Qp, q_scale, cosb, sinb, Qn, NH);
    norm_rope<<<(MR * NKV) / 8, blk>>>(Kp, k_scale, cosb, sinb, Kn, NKV);

    // Causal flash attention (fp32)
    flash_attn<<<dim3(SEQ / 64, NH, BATCH), blk, FLASH_SMEM>>>(Qn, Kn, Vp, Ob);

    // Output projection
    split_rows<<<(MR * DM / 4 + 255) / 256, blk>>>(Ob, Aoh, Aol, MR * DM / 4);
    gemm3s<<<dim3(DM / 128, MR / 128), blk, GEMM_SMEM>>>(Aoh, Aol, WoTh, WoTl, out, DM);
}

// round 4
// speedup vs baseline: 3.7970x; 2.3648x over previous
#include <cuda_runtime.h>
#include <cuda_bf16.h>
#include <cuda_fp16.h>
#include <math.h>
#include <stdint.h>

// Problem constants
constexpr int BATCH = 2;
constexpr int SEQ   = 2048;
constexpr int DM    = 2048;
constexpr int NH    = 16;
constexpr int NKV   = 4;
constexpr int HDIM  = 128;
constexpr int HHALF = 64;
constexpr float EPSV = 1e-6f;
constexpr float SM_SCALE = 0.08838834764831845f; // 1/sqrt(128)
constexpr float SCL_LOG2 = 0.12754245006483662f; // SM_SCALE * log2(e)
constexpr int MR  = BATCH * SEQ;                  // 4096 rows
constexpr int KVD = NKV * HDIM;                   // 512

// ---------------- scratch (device globals — no runtime allocation) --------
__device__ float g_Qp[MR * DM];                   // Q projection fp32
__device__ float g_Kp[MR * KVD];                  // K projection fp32
__device__ __half g_Qh[MR * DM];                  // Q after norm+rope, fp16
__device__ __half g_Kh[MR * KVD];                 // K after norm+rope, fp16
__device__ __half g_Vh[MR * KVD];                 // V projection, fp16

__device__ __nv_bfloat16 g_Aq_h[MR * DM],  g_Aq_l[MR * DM];
__device__ __nv_bfloat16 g_Akv_h[MR * DM], g_Akv_l[MR * DM];
__device__ __nv_bfloat16 g_Ao_h[MR * DM],  g_Ao_l[MR * DM];   // attn out hi/lo
__device__ __nv_bfloat16 g_WqT_h[DM * DM],  g_WqT_l[DM * DM];
__device__ __nv_bfloat16 g_WkT_h[KVD * DM], g_WkT_l[KVD * DM];
__device__ __nv_bfloat16 g_WvT_h[KVD * DM], g_WvT_l[KVD * DM];
__device__ __nv_bfloat16 g_WoT_h[DM * DM],  g_WoT_l[DM * DM];

// ---------------------------------------------------------------------------
// Helpers (baseline PTX only: cp.async, ldmatrix, mma.sync)
// ---------------------------------------------------------------------------
__device__ __forceinline__ uint32_t smem_u32(const void* p) {
    uint32_t a;
    asm("{ .reg .u64 t; cvta.to.shared.u64 t, %1; cvt.u32.u64 %0, t; }"
        : "=r"(a) : "l"(p));
    return a;
}

__device__ __forceinline__ void cp16(uint32_t dst, const void* src) {
    asm volatile("cp.async.cg.shared.global [%0], [%1], 16;" :: "r"(dst), "l"(src));
}
__device__ __forceinline__ void cp_commit() {
    asm volatile("cp.async.commit_group;" ::: "memory");
}
template <int N>
__device__ __forceinline__ void cp_wait() {
    asm volatile("cp.async.wait_group %0;" :: "n"(N) : "memory");
}

__device__ __forceinline__ void ldsm4(uint32_t& r0, uint32_t& r1, uint32_t& r2,
                                      uint32_t& r3, uint32_t addr) {
    asm volatile("ldmatrix.sync.aligned.m8n8.x4.shared.b16 {%0,%1,%2,%3}, [%4];"
                 : "=r"(r0), "=r"(r1), "=r"(r2), "=r"(r3) : "r"(addr));
}
__device__ __forceinline__ void ldsm4t(uint32_t& r0, uint32_t& r1, uint32_t& r2,
                                       uint32_t& r3, uint32_t addr) {
    asm volatile("ldmatrix.sync.aligned.m8n8.x4.trans.shared.b16 {%0,%1,%2,%3}, [%4];"
                 : "=r"(r0), "=r"(r1), "=r"(r2), "=r"(r3) : "r"(addr));
}

__device__ __forceinline__ void mma_bf16(float* c, const uint32_t* a,
                                         const uint32_t* b) {
    asm volatile(
        "mma.sync.aligned.m16n8k16.row.col.f32.bf16.bf16.f32 "
        "{%0,%1,%2,%3}, {%4,%5,%6,%7}, {%8,%9}, {%0,%1,%2,%3};"
        : "+f"(c[0]), "+f"(c[1]), "+f"(c[2]), "+f"(c[3])
        : "r"(a[0]), "r"(a[1]), "r"(a[2]), "r"(a[3]), "r"(b[0]), "r"(b[1]));
}
__device__ __forceinline__ void mma_fp16(float* c, const uint32_t* a,
                                         uint32_t b0, uint32_t b1) {
    asm volatile(
        "mma.sync.aligned.m16n8k16.row.col.f32.f16.f16.f32 "
        "{%0,%1,%2,%3}, {%4,%5,%6,%7}, {%8,%9}, {%0,%1,%2,%3};"
        : "+f"(c[0]), "+f"(c[1]), "+f"(c[2]), "+f"(c[3])
        : "r"(a[0]), "r"(a[1]), "r"(a[2]), "r"(a[3]), "r"(b0), "r"(b1));
}

// ---------------------------------------------------------------------------
// hi/lo bf16 split, elementwise
// ---------------------------------------------------------------------------
__global__ __launch_bounds__(256) void split_rows(
    const float* __restrict__ X, __nv_bfloat16* __restrict__ Hh,
    __nv_bfloat16* __restrict__ Ll, int n4)
{
    int i = blockIdx.x * blockDim.x + threadIdx.x;
    if (i >= n4) return;
    float4 v = ((const float4*)X)[i];
    __nv_bfloat16 h0 = __float2bfloat16(v.x);
    __nv_bfloat16 h1 = __float2bfloat16(v.y);
    __nv_bfloat16 h2 = __float2bfloat16(v.z);
    __nv_bfloat16 h3 = __float2bfloat16(v.w);
    __nv_bfloat162* Hp = (__nv_bfloat162*)Hh;
    Hp[2 * i]     = __nv_bfloat162(h0, h1);
    Hp[2 * i + 1] = __nv_bfloat162(h2, h3);
    __nv_bfloat16 l0 = __float2bfloat16(v.x - __bfloat162float(h0));
    __nv_bfloat16 l1 = __float2bfloat16(v.y - __bfloat162float(h1));
    __nv_bfloat16 l2 = __float2bfloat16(v.z - __bfloat162float(h2));
    __nv_bfloat16 l3 = __float2bfloat16(v.w - __bfloat162float(h3));
    __nv_bfloat162* Lp = (__nv_bfloat162*)Ll;
    Lp[2 * i]     = __nv_bfloat162(l0, l1);
    Lp[2 * i + 1] = __nv_bfloat162(l2, l3);
}

// ---------------------------------------------------------------------------
// Transpose + hi/lo split: W[K,N] fp32 -> WT_hi/WT_lo [N,K] bf16
// ---------------------------------------------------------------------------
__global__ __launch_bounds__(256) void split_transpose(
    const float* __restrict__ W, __nv_bfloat16* __restrict__ TH,
    __nv_bfloat16* __restrict__ TL, int K, int N)
{
    __shared__ float tile[32][33];
    const int k0 = blockIdx.x * 32, n0 = blockIdx.y * 32;
    const int tx = threadIdx.x, ty = threadIdx.y;     // 32 x 8
#pragma unroll
    for (int i = 0; i < 4; i++)
        tile[ty + i * 8][tx] = W[(size_t)(k0 + ty + i * 8) * N + n0 + tx];
    __syncthreads();
#pragma unroll
    for (int i = 0; i < 4; i++) {
        float v = tile[tx][ty + i * 8];
        int n = n0 + ty + i * 8;
        __nv_bfloat16 h = __float2bfloat16(v);
        TH[(size_t)n * K + k0 + tx] = h;
        TL[(size_t)n * K + k0 + tx] = __float2bfloat16(v - __bfloat162float(h));
    }
}

// ---------------------------------------------------------------------------
// bf16 tensor-core GEMM, 3-term hi/lo split (mma.sync). Optional fp16 output.
// ---------------------------------------------------------------------------
constexpr int LDT    = 72;
constexpr int ABYTES = 128 * LDT * 2;
constexpr int STAGEB = 2 * ABYTES;
constexpr int GEMM_SMEM = 2 * STAGEB;

template <bool HALF_OUT>
__global__ __launch_bounds__(256, 2) void gemm3s(
    const __nv_bfloat16* __restrict__ Ahi, const __nv_bfloat16* __restrict__ Alo,
    const __nv_bfloat16* __restrict__ Bhi, const __nv_bfloat16* __restrict__ Blo,
    void* __restrict__ Cv, int N)
{
    extern __shared__ __align__(16) char smg[];
    const uint32_t sb = smem_u32(smg);
    const int t = threadIdx.x, lane = t & 31, wid = t >> 5;
    const int wm = wid & 1, wn = wid >> 1;
    const int m0 = blockIdx.y * 128, n0 = blockIdx.x * 128;

    float acc[4][4][4] = {};

    const int lrow = t >> 3;
    const int lch  = t & 7;
    const int NIT = 96;

    auto load_stage = [&](int it, int s) {
        const int sec  = it >> 5;
        const int koff = (it & 31) << 6;
        const __nv_bfloat16* Ag = (sec == 1 ? Alo : Ahi);
        const __nv_bfloat16* Bg = (sec == 2 ? Blo : Bhi);
        const uint32_t Ab = sb + s * STAGEB;
        const uint32_t Bb = Ab + ABYTES;
#pragma unroll
        for (int i = 0; i < 4; i++) {
            const int row = lrow + i * 32;
            cp16(Ab + row * (LDT * 2) + lch * 16,
                 Ag + (size_t)(m0 + row) * DM + koff + lch * 8);
            cp16(Bb + row * (LDT * 2) + lch * 16,
                 Bg + (size_t)(n0 + row) * DM + koff + lch * 8);
        }
        cp_commit();
    };

    load_stage(0, 0);

    const uint32_t a_off = (uint32_t)((wm * 64 + (lane & 15)) * (LDT * 2) +
                                      ((lane >> 4) << 4));
    const uint32_t b_off = (uint32_t)((wn * 32 + ((lane >> 4) << 3) + (lane & 7)) * (LDT * 2) +
                                      (((lane >> 3) & 1) << 4));

    for (int it = 0; it < NIT; it++) {
        if (it + 1 < NIT) {
            load_stage(it + 1, (it + 1) & 1);
            cp_wait<1>();
        } else {
            cp_wait<0>();
        }
        __syncthreads();

        const uint32_t Ab = sb + (it & 1) * STAGEB;
        const uint32_t Bb = Ab + ABYTES;

#pragma unroll
        for (int ks = 0; ks < 4; ks++) {
            uint32_t a[4][4];
            uint32_t b[4][2];
#pragma unroll
            for (int i = 0; i < 4; i++)
                ldsm4(a[i][0], a[i][1], a[i][2], a[i][3],
                      Ab + a_off + i * 16 * (LDT * 2) + ks * 32);
#pragma unroll
            for (int j = 0; j < 2; j++) {
                uint32_t r0, r1, r2, r3;
                ldsm4(r0, r1, r2, r3,
                      Bb + b_off + j * 16 * (LDT * 2) + ks * 32);
                b[j * 2][0] = r0; b[j * 2][1] = r1;
                b[j * 2 + 1][0] = r2; b[j * 2 + 1][1] = r3;
            }
#pragma unroll
            for (int i = 0; i < 4; i++)
#pragma unroll
                for (int j = 0; j < 4; j++)
                    mma_bf16(acc[i][j], a[i], b[j]);
        }
        __syncthreads();
    }

#pragma unroll
    for (int i = 0; i < 4; i++) {
#pragma unroll
        for (int j = 0; j < 4; j++) {
            const int m = m0 + wm * 64 + i * 16 + (lane >> 2);
            const int n = n0 + wn * 32 + j * 8 + ((lane & 3) << 1);
            if (HALF_OUT) {
                __half* C = (__half*)Cv;
                __half2 h0 = __floats2half2_rn(acc[i][j][0], acc[i][j][1]);
                __half2 h1 = __floats2half2_rn(acc[i][j][2], acc[i][j][3]);
                *(__half2*)&C[(size_t)m * N + n] = h0;
                *(__half2*)&C[(size_t)(m + 8) * N + n] = h1;
            } else {
                float* C = (float*)Cv;
                *(float2*)&C[(size_t)m * N + n] =
                    make_float2(acc[i][j][0], acc[i][j][1]);
                *(float2*)&C[(size_t)(m + 8) * N + n] =
                    make_float2(acc[i][j][2], acc[i][j][3]);
            }
        }
    }
}

// ---------------------------------------------------------------------------
// Fused per-head RMSNorm + RoPE, fp32 in -> fp16 out
// ---------------------------------------------------------------------------
__global__ __launch_bounds__(256) void norm_rope_h(
    const float* __restrict__ P, const float* __restrict__ scale,
    const float* __restrict__ cs, const float* __restrict__ sn,
    __half* __restrict__ out, int nh)
{
    const int gw   = (int)((blockIdx.x * blockDim.x + threadIdx.x) >> 5);
    const int lane = threadIdx.x & 31;
    const int h  = gw % nh;
    const int bt = gw / nh;
    const int tt = bt % SEQ;

    const size_t base = (size_t)bt * (nh * HDIM) + (size_t)h * HDIM;
    const int d = lane * 2;

    float2 lo = *(const float2*)&P[base + d];
    float2 hi = *(const float2*)&P[base + d + HHALF];

    float ss = lo.x * lo.x + lo.y * lo.y + hi.x * hi.x + hi.y * hi.y;
#pragma unroll
    for (int o = 16; o > 0; o >>= 1)
        ss += __shfl_xor_sync(0xffffffffu, ss, o);
    const float inv = rsqrtf(ss * (1.0f / HDIM) + EPSV);

    const float g0 = (1.0f + scale[d])             * inv;
    const float g1 = (1.0f + scale[d + 1])         * inv;
    const float g2 = (1.0f + scale[d + HHALF])     * inv;
    const float g3 = (1.0f + scale[d + 1 + HHALF]) * inv;

    const float x1a = lo.x * g0, x1b = lo.y * g1;
    const float x2a = hi.x * g2, x2b = hi.y * g3;

    const float c0 = cs[(size_t)tt * HHALF + d];
    const float c1 = cs[(size_t)tt * HHALF + d + 1];
    const float s0 = sn[(size_t)tt * HHALF + d];
    const float s1 = sn[(size_t)tt * HHALF + d + 1];

    *(__half2*)&out[base + d] =
        __floats2half2_rn(x1a * c0 - x2a * s0, x1b * c1 - x2b * s1);
    *(__half2*)&out[base + d + HHALF] =
        __floats2half2_rn(x2a * c0 + x1a * s0, x2b * c1 + x1b * s1);
}

// ---------------------------------------------------------------------------
// Flash attention via mma.sync fp16 (FA2 style).
// Block: 256 threads (8 warps), 128-query tile for one (b,h).
// K/V 64x128 fp16 tiles, double-buffered cp.async. Online softmax in log2.
// Epilogue writes bf16 hi/lo pair for the Wo split-GEMM.
// ---------------------------------------------------------------------------
constexpr int LDH  = 136;                  // halves per smem row (128+8)
constexpr int KSTG = 64 * LDH * 2;         // 17408 B (one K or V tile)
constexpr int FSTG = 2 * KSTG;             // 34816 B per stage
constexpr int FLASH_SMEM = 2 * FSTG;       // 69632 B

__global__ __launch_bounds__(256) void flash_mma(
    const __half* __restrict__ Qh, const __half* __restrict__ Kh,
    const __half* __restrict__ Vh,
    __nv_bfloat16* __restrict__ Oh, __nv_bfloat16* __restrict__ Ol)
{
    extern __shared__ __align__(16) char smf[];
    const uint32_t sb = smem_u32(smf);
    const int t = threadIdx.x, lane = t & 31, wid = t >> 5;
    const int qt = (SEQ / 128 - 1) - blockIdx.x;   // heavy tiles first
    const int h = blockIdx.y, b = blockIdx.z;
    const int q0 = qt * 128;
    const int kh = h >> 2;

    const __half* Qg = Qh + (size_t)(b * SEQ + q0) * DM + h * HDIM;
    const __half* Kg = Kh + (size_t)(b * SEQ) * KVD + kh * HDIM;
    const __half* Vg = Vh + (size_t)(b * SEQ) * KVD + kh * HDIM;

    // ---- Q tile -> smem -> register fragments (once)
    {
        const int row = t >> 1;
        const int cb  = (t & 1) * 8;
#pragma unroll
        for (int i = 0; i < 8; i++)
            cp16(sb + row * (LDH * 2) + (cb + i) * 16,
                 Qg + (size_t)row * DM + (size_t)(cb + i) * 8);
        cp_commit();
    }
    cp_wait<0>();
    __syncthreads();

    uint32_t qf[8][4];
    {
        const uint32_t a_off = sb + (wid * 16 + (lane & 15)) * (LDH * 2) +
                               ((lane >> 4) << 4);
#pragma unroll
        for (int ks = 0; ks < 8; ks++)
            ldsm4(qf[ks][0], qf[ks][1], qf[ks][2], qf[ks][3], a_off + ks * 32);
    }
    __syncthreads();   // Q smem region free

    float mrow[2] = {-1e30f, -1e30f};   // running max (log2 domain)
    float lrow[2] = {0.0f, 0.0f};       // running denom
    float o[16][4] = {};

    const int ntk = 2 * qt + 2;
    auto load_kv = [&](int kt, int s) {
        const int k0 = kt * 64;
        const int row = t >> 2;
        const uint32_t Kb = sb + s * FSTG;
        const uint32_t Vb = Kb + KSTG;
#pragma unroll
        for (int i = 0; i < 4; i++) {
            const int c = (t & 3) + i * 4;
            cp16(Kb + row * (LDH * 2) + c * 16,
                 Kg + (size_t)(k0 + row) * KVD + (size_t)c * 8);
            cp16(Vb + row * (LDH * 2) + c * 16,
                 Vg + (size_t)(k0 + row) * KVD + (size_t)c * 8);
        }
        cp_commit();
    };
    load_kv(0, 0);

    const int wrow_hi = q0 + wid * 16 + 15;       // warp's max query row
    const int myrow   = q0 + wid * 16 + (lane >> 2);

    for (int kt = 0; kt < ntk; kt++) {
        if (kt + 1 < ntk) { load_kv(kt + 1, (kt + 1) & 1); cp_wait<1>(); }
        else              { cp_wait<0>(); }
        __syncthreads();

        const int k0 = kt * 64;
        const bool active = (k0 <= wrow_hi);
        if (active) {
            const uint32_t Kb = sb + (kt & 1) * FSTG;
            const uint32_t Vb = Kb + KSTG;

            // ---- S = Q K^T (warp: 16 rows x 64 keys)
            float sc[8][4] = {};
#pragma unroll
            for (int j = 0; j < 4; j++) {
                const uint32_t kb = Kb +
                    (j * 16 + ((lane >> 4) << 3) + (lane & 7)) * (LDH * 2) +
                    (((lane >> 3) & 1) << 4);
#pragma unroll
                for (int ks = 0; ks < 8; ks++) {
                    uint32_t r0, r1, r2, r3;
                    ldsm4(r0, r1, r2, r3, kb + ks * 32);
                    mma_fp16(sc[2 * j],     qf[ks], r0, r1);
                    mma_fp16(sc[2 * j + 1], qf[ks], r2, r3);
                }
            }

            // ---- scale (log2 domain) + causal mask + row max
            float tmax[2] = {-1e30f, -1e30f};
            const bool diag = (k0 + 63 > q0 + wid * 16);  // any masking possible
#pragma unroll
            for (int nt = 0; nt < 8; nt++) {
                const int kc = k0 + nt * 8 + ((lane & 3) << 1);
#pragma unroll
                for (int hf = 0; hf < 2; hf++) {
                    const int r = myrow + hf * 8;
                    float v0 = sc[nt][hf * 2]     * SCL_LOG2;
                    float v1 = sc[nt][hf * 2 + 1] * SCL_LOG2;
                    if (diag) {
                        if (kc     > r) v0 = -1e30f;
                        if (kc + 1 > r) v1 = -1e30f;
                    }
                    sc[nt][hf * 2]     = v0;
                    sc[nt][hf * 2 + 1] = v1;
                    tmax[hf] = fmaxf(tmax[hf], fmaxf(v0, v1));
                }
            }
#pragma unroll
            for (int off = 1; off <= 2; off <<= 1) {
                tmax[0] = fmaxf(tmax[0], __shfl_xor_sync(0xffffffffu, tmax[0], off));
                tmax[1] = fmaxf(tmax[1], __shfl_xor_sync(0xffffffffu, tmax[1], off));
            }
            const float mn0 = fmaxf(mrow[0], tmax[0]);
            const float mn1 = fmaxf(mrow[1], tmax[1]);
            const float al0 = exp2f(mrow[0] - mn0);
            const float al1 = exp2f(mrow[1] - mn1);
            mrow[0] = mn0; mrow[1] = mn1;

            // ---- P = exp2(s - m), pack to fp16 A-fragments, row sums
            float rs[2] = {0.0f, 0.0f};
            uint32_t pf[8][2];
#pragma unroll
            for (int nt = 0; nt < 8; nt++) {
                const float e0 = exp2f(sc[nt][0] - mn0);
                const float e1 = exp2f(sc[nt][1] - mn0);
                const float e2 = exp2f(sc[nt][2] - mn1);
                const float e3 = exp2f(sc[nt][3] - mn1);
                rs[0] += e0 + e1;
                rs[1] += e2 + e3;
                __half2 p0 = __floats2half2_rn(e0, e1);
                __half2 p1 = __floats2half2_rn(e2, e3);
                pf[nt][0] = *(uint32_t*)&p0;
                pf[nt][1] = *(uint32_t*)&p1;
            }
#pragma unroll
            for (int off = 1; off <= 2; off <<= 1) {
                rs[0] += __shfl_xor_sync(0xffffffffu, rs[0], off);
                rs[1] += __shfl_xor_sync(0xffffffffu, rs[1], off);
            }
            lrow[0] = lrow[0] * al0 + rs[0];
            lrow[1] = lrow[1] * al1 + rs[1];

            // ---- rescale O
#pragma unroll
            for (int nt = 0; nt < 16; nt++) {
                o[nt][0] *= al0; o[nt][1] *= al0;
                o[nt][2] *= al1; o[nt][3] *= al1;
            }

            // ---- O += P V
#pragma unroll
            for (int ks = 0; ks < 4; ks++) {
                uint32_t a[4] = {pf[2 * ks][0], pf[2 * ks][1],
                                 pf[2 * ks + 1][0], pf[2 * ks + 1][1]};
                const uint32_t vrow = Vb + (ks * 16 + (lane & 15)) * (LDH * 2) +
                                      (((lane >> 4) << 3) << 1);
#pragma unroll
                for (int vg = 0; vg < 8; vg++) {
                    uint32_t b0, b1, b2, b3;
                    ldsm4t(b0, b1, b2, b3, vrow + vg * 32);
                    mma_fp16(o[2 * vg],     a, b0, b1);
                    mma_fp16(o[2 * vg + 1], a, b2, b3);
                }
            }
        }
        __syncthreads();
    }

    // ---- epilogue: normalize + bf16 hi/lo write
    const float inv0 = 1.0f / lrow[0];
    const float inv1 = 1.0f / lrow[1];
    const int colb = h * HDIM + ((lane & 3) << 1);
#pragma unroll
    for (int nt = 0; nt < 16; nt++) {
        const size_t i0 = (size_t)(b * SEQ + myrow) * DM + colb + nt * 8;
        const size_t i1 = i0 + (size_t)8 * DM;
        float x0 = o[nt][0] * inv0, x1 = o[nt][1] * inv0;
        float x2 = o[nt][2] * inv1, x3 = o[nt][3] * inv1;
        __nv_bfloat16 h0 = __float2bfloat16(x0), h1 = __float2bfloat16(x1);
        __nv_bfloat16 h2 = __float2bfloat16(x2), h3 = __float2bfloat16(x3);
        *(__nv_bfloat162*)&Oh[i0] = __nv_bfloat162(h0, h1);
        *(__nv_bfloat162*)&Oh[i1] = __nv_bfloat162(h2, h3);
        *(__nv_bfloat162*)&Ol[i0] = __nv_bfloat162(
            __float2bfloat16(x0 - __bfloat162float(h0)),
            __float2bfloat16(x1 - __bfloat162float(h1)));
        *(__nv_bfloat162*)&Ol[i1] = __nv_bfloat162(
            __float2bfloat16(x2 - __bfloat162float(h2)),
            __float2bfloat16(x3 - __bfloat162float(h3)));
    }
}

// ---------------------------------------------------------------------------
// Launch
// ---------------------------------------------------------------------------
extern "C" void kernel_launch(void* const* d_in, const int* in_sizes, int n_in,
                              void* d_out, int out_size)
{
    const float* q_input  = (const float*)d_in[0];
    const float* kv_input = (const float*)d_in[1];
    const float* cosb     = (const float*)d_in[3];
    const float* sinb     = (const float*)d_in[4];
    const float* Wq       = (const float*)d_in[5];
    const float* Wk       = (const float*)d_in[6];
    const float* Wv       = (const float*)d_in[7];
    const float* q_scale  = (const float*)d_in[8];
    const float* k_scale  = (const float*)d_in[9];
    const float* Wo       = (const float*)d_in[10];
    float* out = (float*)d_out;

    float *Qp, *Kp;
    __half *Qh, *Kh, *Vh;
    cudaGetSymbolAddress((void**)&Qp, g_Qp);
    cudaGetSymbolAddress((void**)&Kp, g_Kp);
    cudaGetSymbolAddress((void**)&Qh, g_Qh);
    cudaGetSymbolAddress((void**)&Kh, g_Kh);
    cudaGetSymbolAddress((void**)&Vh, g_Vh);

    __nv_bfloat16 *Aqh, *Aql, *Akh, *Akl, *Aoh, *Aol;
    __nv_bfloat16 *WqTh, *WqTl, *WkTh, *WkTl, *WvTh, *WvTl, *WoTh, *WoTl;
    cudaGetSymbolAddress((void**)&Aqh, g_Aq_h);
    cudaGetSymbolAddress((void**)&Aql, g_Aq_l);
    cudaGetSymbolAddress((void**)&Akh, g_Akv_h);
    cudaGetSymbolAddress((void**)&Akl, g_Akv_l);
    cudaGetSymbolAddress((void**)&Aoh, g_Ao_h);
    cudaGetSymbolAddress((void**)&Aol, g_Ao_l);
    cudaGetSymbolAddress((void**)&WqTh, g_WqT_h);
    cudaGetSymbolAddress((void**)&WqTl, g_WqT_l);
    cudaGetSymbolAddress((void**)&WkTh, g_WkT_h);
    cudaGetSymbolAddress((void**)&WkTl, g_WkT_l);
    cudaGetSymbolAddress((void**)&WvTh, g_WvT_h);
    cudaGetSymbolAddress((void**)&WvTl, g_WvT_l);
    cudaGetSymbolAddress((void**)&WoTh, g_WoT_h);
    cudaGetSymbolAddress((void**)&WoTl, g_WoT_l);

    cudaFuncSetAttribute(gemm3s<false>, cudaFuncAttributeMaxDynamicSharedMemorySize,
                         GEMM_SMEM);
    cudaFuncSetAttribute(gemm3s<true>, cudaFuncAttributeMaxDynamicSharedMemorySize,
                         GEMM_SMEM);
    cudaFuncSetAttribute(flash_mma, cudaFuncAttributeMaxDynamicSharedMemorySize,
                         FLASH_SMEM);

    dim3 blk(256);

    // hi/lo splits of activations and (transposed) weights
    split_rows<<<(MR * DM / 4 + 255) / 256, blk>>>(q_input, Aqh, Aql, MR * DM / 4);
    split_rows<<<(MR * DM / 4 + 255) / 256, blk>>>(kv_input, Akh, Akl, MR * DM / 4);
    split_transpose<<<dim3(DM / 32, DM / 32), dim3(32, 8)>>>(Wq, WqTh, WqTl, DM, DM);
    split_transpose<<<dim3(DM / 32, KVD / 32), dim3(32, 8)>>>(Wk, WkTh, WkTl, DM, KVD);
    split_transpose<<<dim3(DM / 32, KVD / 32), dim3(32, 8)>>>(Wv, WvTh, WvTl, DM, KVD);
    split_transpose<<<dim3(DM / 32, DM / 32), dim3(32, 8)>>>(Wo, WoTh, WoTl, DM, DM);

    // projections: Q,K fp32 out (need rmsnorm), V straight to fp16
    gemm3s<false><<<dim3(DM / 128, MR / 128), blk, GEMM_SMEM>>>(Aqh, Aql, WqTh, WqTl, Qp, DM);
    gemm3s<false><<<dim3(KVD / 128, MR / 128), blk, GEMM_SMEM>>>(Akh, Akl, WkTh, WkTl, Kp, KVD);
    gemm3s<true><<<dim3(KVD / 128, MR / 128), blk, GEMM_SMEM>>>(Akh, Akl, WvTh, WvTl, Vh, KVD);

    // RMSNorm + RoPE -> fp16
    norm_rope_h<<<(MR * NH) / 8, blk>>>(Qp, q_scale, cosb, sinb, Qh, NH);
    norm_rope_h<<<(MR * NKV) / 8, blk>>>(Kp, k_scale, cosb, sinb, Kh, NKV);

    // Flash attention (fp16 tensor cores), writes bf16 hi/lo directly
    flash_mma<<<dim3(SEQ / 128, NH, BATCH), blk, FLASH_SMEM>>>(Qh, Kh, Vh, Aoh, Aol);

    // Output projection
    gemm3s<false><<<dim3(DM / 128, MR / 128), blk, GEMM_SMEM>>>(Aoh, Aol, WoTh, WoTl, out, DM);
}